// round 2
// baseline (speedup 1.0000x reference)
#include <cuda_runtime.h>

// Verblizer: per-token argmax(20) -> expert Linear(2,2) -> softmax(2)
// -> y, plus permuted copy y2 (pu rows first, then non-pu rows in order).
//
// Output layout: d_out[0 .. 2S)   = y   (row-major [S,2])
//                d_out[2S .. 4S)  = y2  (row-major [S,2])

#define THREADS        256
#define TOK_PER_THREAD 4
#define CHUNK          (THREADS * TOK_PER_THREAD)   // 1024 tokens per block

__global__ __launch_bounds__(THREADS)
void verblizer_kernel(const float*  __restrict__ x,
                      const float*  __restrict__ h,
                      const float*  __restrict__ W,
                      const float*  __restrict__ b,
                      const int*    __restrict__ pu,
                      int S, int P,
                      float* __restrict__ out)
{
    __shared__ float4 sW[20];   // (W[e][0][0], W[e][0][1], W[e][1][0], W[e][1][1])
    __shared__ float2 sB[20];
    __shared__ int    s_lb0;

    const int tid = threadIdx.x;
    if (tid < 20) {
        sW[tid] = reinterpret_cast<const float4*>(W)[tid];
        sB[tid] = reinterpret_cast<const float2*>(b)[tid];
    }

    const int block_start = blockIdx.x * CHUNK;

    if (tid == 0) {
        // lower_bound(pu, block_start) over the full array (amortized per 1024 tokens)
        int lo = 0, hi = P;
        while (lo < hi) {
            int mid = (lo + hi) >> 1;
            if (__ldg(pu + mid) < block_start) lo = mid + 1; else hi = mid;
        }
        s_lb0 = lo;
    }
    __syncthreads();

    const int s0 = block_start + tid * TOK_PER_THREAD;
    if (s0 >= S) return;

    // Narrow per-thread lower_bound(pu, s0): lb(s0) in [lb0, lb0 + (s0-block_start)]
    int lo = s_lb0;
    int hi = min(P, s_lb0 + CHUNK);
    while (lo < hi) {
        int mid = (lo + hi) >> 1;
        if (__ldg(pu + mid) < s0) lo = mid + 1; else hi = mid;
    }
    int lb = lo;   // #pu strictly below current token

    float2* __restrict__ outy  = reinterpret_cast<float2*>(out);
    float2* __restrict__ outy2 = reinterpret_cast<float2*>(out + (size_t)2 * S);

    #pragma unroll
    for (int k = 0; k < TOK_PER_THREAD; k++) {
        const int s = s0 + k;
        if (s >= S) break;

        // ---- exact argmax over 20 f32 (first-index tie-break, matches jnp.argmax) ----
        const float4* xr = reinterpret_cast<const float4*>(x + (size_t)s * 20);
        const float4 q0 = xr[0], q1 = xr[1], q2 = xr[2], q3 = xr[3], q4 = xr[4];

        // per-quad maxes (all 4 lanes each!)
        const float g0 = fmaxf(fmaxf(q0.x, q0.y), fmaxf(q0.z, q0.w));
        const float g1 = fmaxf(fmaxf(q1.x, q1.y), fmaxf(q1.z, q1.w));
        const float g2 = fmaxf(fmaxf(q2.x, q2.y), fmaxf(q2.z, q2.w));
        const float g3 = fmaxf(fmaxf(q3.x, q3.y), fmaxf(q3.z, q3.w));
        const float g4 = fmaxf(fmaxf(q4.x, q4.y), fmaxf(q4.z, q4.w));
        // global max
        const float M  = fmaxf(g4, fmaxf(fmaxf(g0, g1), fmaxf(g2, g3)));

        // smallest group index whose max equals M (downward scan -> first group wins)
        int gi = 4;
        gi = (g3 == M) ? 3 : gi;
        gi = (g2 == M) ? 2 : gi;
        gi = (g1 == M) ? 1 : gi;
        gi = (g0 == M) ? 0 : gi;

        // reload winning quad (L1-hot) to avoid register-indexed selects
        const float4 qw = xr[gi];
        int li = 3;
        li = (qw.z == M) ? 2 : li;
        li = (qw.y == M) ? 1 : li;
        li = (qw.x == M) ? 0 : li;
        const int e = gi * 4 + li;

        // ---- expert Linear(2,2) + softmax(2) ----
        const float2 hv = reinterpret_cast<const float2*>(h)[s];
        const float4 w  = sW[e];
        const float2 bb = sB[e];
        const float y0 = fmaf(hv.x, w.x, fmaf(hv.y, w.y, bb.x));
        const float y1 = fmaf(hv.x, w.z, fmaf(hv.y, w.w, bb.y));
        const float ed  = __expf(y1 - y0);             // softmax over 2 via sigmoid
        const float inv = __fdividef(1.0f, 1.0f + ed);
        float2 yo;
        yo.x = inv;
        yo.y = ed * inv;

        outy[s] = yo;

        // ---- permutation destination ----
        // lb == #pu < s ; is_pu iff pu[lb] == s
        const int cur   = (lb < P) ? __ldg(pu + lb) : 0x7fffffff;
        const bool ispu = (cur == s);
        const int dest  = ispu ? lb : (P + s - lb);
        outy2[dest] = yo;
        lb += ispu ? 1 : 0;
    }
}

extern "C" void kernel_launch(void* const* d_in, const int* in_sizes, int n_in,
                              void* d_out, int out_size)
{
    const float* x  = (const float*)d_in[0];   // [1, S, 20]
    const float* h  = (const float*)d_in[1];   // [S, 2]
    const float* W  = (const float*)d_in[2];   // [20, 2, 2]
    const float* b  = (const float*)d_in[3];   // [20, 2]
    const int*   pu = (const int*)  d_in[4];   // [P]

    const int S = in_sizes[1] / 2;
    const int P = in_sizes[4];

    const int blocks = (S + CHUNK - 1) / CHUNK;
    verblizer_kernel<<<blocks, THREADS>>>(x, h, W, b, pu, S, P, (float*)d_out);
}

// round 3
// speedup vs baseline: 1.0042x; 1.0042x over previous
#include <cuda_runtime.h>

// Verblizer: per-token argmax(20) -> expert Linear(2,2) -> softmax(2)
// -> y, plus permuted copy y2 (pu rows first, then non-pu rows in order).
//
// Output layout: d_out[0 .. 2S)   = y   (row-major [S,2])
//                d_out[2S .. 4S)  = y2  (row-major [S,2])
//
// Two launches:
//   1) lb_kernel: per block-boundary lower_bound(pu, boundary) -> g_lb0[]
//   2) verblizer_kernel: streaming pass; pu window staged in smem, all
//      searches hit LDS instead of serial global dependent loads.

#define THREADS        256
#define TOK_PER_THREAD 4
#define CHUNK          (THREADS * TOK_PER_THREAD)   // 1024 tokens per block
#define MAXB           65537

__device__ int g_lb0[MAXB];

__global__ void lb_kernel(const int* __restrict__ pu, int P, int nblocks)
{
    const int i = blockIdx.x * blockDim.x + threadIdx.x;
    if (i > nblocks) return;
    const int target = i * CHUNK;
    int lo = 0, hi = P;
    while (lo < hi) {
        int mid = (lo + hi) >> 1;
        if (__ldg(pu + mid) < target) lo = mid + 1; else hi = mid;
    }
    g_lb0[i] = lo;
}

__global__ __launch_bounds__(THREADS)
void verblizer_kernel(const float*  __restrict__ x,
                      const float*  __restrict__ h,
                      const float*  __restrict__ W,
                      const float*  __restrict__ b,
                      const int*    __restrict__ pu,
                      int S, int P,
                      float* __restrict__ out)
{
    __shared__ float4 sW[20];
    __shared__ float2 sB[20];
    __shared__ int    spu[CHUNK];

    const int tid = threadIdx.x;
    const int bs  = blockIdx.x * CHUNK;

    const int lb0    = g_lb0[blockIdx.x];
    const int lb_end = g_lb0[blockIdx.x + 1];
    const int n      = lb_end - lb0;          // pu entries falling in this block (<= CHUNK)

    if (tid < 20) {
        sW[tid] = reinterpret_cast<const float4*>(W)[tid];
        sB[tid] = reinterpret_cast<const float2*>(b)[tid];
    }
    for (int i = tid; i < n; i += THREADS) spu[i] = __ldg(pu + lb0 + i);
    __syncthreads();

    const int s0 = bs + tid * TOK_PER_THREAD;
    if (s0 >= S) return;

    // per-thread lower_bound within the smem window (LDS-hot, <=10 steps)
    int lo = 0, hi = n;
    while (lo < hi) {
        int mid = (lo + hi) >> 1;
        if (spu[mid] < s0) lo = mid + 1; else hi = mid;
    }
    int lbi = lo;                              // local index into window

    float2* __restrict__ outy  = reinterpret_cast<float2*>(out);
    float2* __restrict__ outy2 = reinterpret_cast<float2*>(out + (size_t)2 * S);
    const float4* __restrict__ xr4 = reinterpret_cast<const float4*>(x) + (size_t)s0 * 5;
    const float2* __restrict__ h2  = reinterpret_cast<const float2*>(h);

    const bool full = (s0 + TOK_PER_THREAD <= S);
    const int  kmax = full ? TOK_PER_THREAD : (S - s0);

    #pragma unroll
    for (int k = 0; k < TOK_PER_THREAD; k++) {
        if (!full && k >= kmax) break;
        const int s = s0 + k;

        // ---- exact argmax over 20 f32 (first-index tie-break, matches jnp.argmax) ----
        const float4 q0 = xr4[5*k+0], q1 = xr4[5*k+1], q2 = xr4[5*k+2],
                     q3 = xr4[5*k+3], q4 = xr4[5*k+4];

        const float g0 = fmaxf(fmaxf(q0.x, q0.y), fmaxf(q0.z, q0.w));
        const float g1 = fmaxf(fmaxf(q1.x, q1.y), fmaxf(q1.z, q1.w));
        const float g2 = fmaxf(fmaxf(q2.x, q2.y), fmaxf(q2.z, q2.w));
        const float g3 = fmaxf(fmaxf(q3.x, q3.y), fmaxf(q3.z, q3.w));
        const float g4 = fmaxf(fmaxf(q4.x, q4.y), fmaxf(q4.z, q4.w));
        const float M  = fmaxf(g4, fmaxf(fmaxf(g0, g1), fmaxf(g2, g3)));

        int gi = 4;
        gi = (g3 == M) ? 3 : gi;
        gi = (g2 == M) ? 2 : gi;
        gi = (g1 == M) ? 1 : gi;
        gi = (g0 == M) ? 0 : gi;

        const float4 qw = xr4[5*k + gi];       // L1-hot reload of winning quad
        int li = 3;
        li = (qw.z == M) ? 2 : li;
        li = (qw.y == M) ? 1 : li;
        li = (qw.x == M) ? 0 : li;
        const int e = gi * 4 + li;

        // ---- expert Linear(2,2) + softmax(2) ----
        const float2 hv = h2[s];
        const float4 w  = sW[e];
        const float2 bb = sB[e];
        const float y0 = fmaf(hv.x, w.x, fmaf(hv.y, w.y, bb.x));
        const float y1 = fmaf(hv.x, w.z, fmaf(hv.y, w.w, bb.y));
        const float ed  = __expf(y1 - y0);
        const float inv = __fdividef(1.0f, 1.0f + ed);
        float2 yo;
        yo.x = inv;
        yo.y = ed * inv;

        outy[s] = yo;

        // ---- permutation destination (pu compare from smem window) ----
        const int  cur  = (lbi < n) ? spu[lbi] : 0x7fffffff;
        const bool ispu = (cur == s);
        const int  lb   = lb0 + lbi;           // #pu strictly below s
        const int  dest = ispu ? lb : (P + s - lb);
        outy2[dest] = yo;
        lbi += ispu ? 1 : 0;
    }
}

extern "C" void kernel_launch(void* const* d_in, const int* in_sizes, int n_in,
                              void* d_out, int out_size)
{
    const float* x  = (const float*)d_in[0];   // [1, S, 20]
    const float* h  = (const float*)d_in[1];   // [S, 2]
    const float* W  = (const float*)d_in[2];   // [20, 2, 2]
    const float* b  = (const float*)d_in[3];   // [20, 2]
    const int*   pu = (const int*)  d_in[4];   // [P]

    const int S = in_sizes[1] / 2;
    const int P = in_sizes[4];

    const int blocks = (S + CHUNK - 1) / CHUNK;

    lb_kernel<<<(blocks + 1 + 255) / 256, 256>>>(pu, P, blocks);
    verblizer_kernel<<<blocks, THREADS>>>(x, h, W, b, pu, S, P, (float*)d_out);
}

// round 4
// speedup vs baseline: 1.7784x; 1.7709x over previous
#include <cuda_runtime.h>
#include <cstdint>

// Verblizer: per-token argmax(20) -> expert Linear(2,2) -> softmax(2) -> y,
// plus permuted copy y2 (pu rows first, then non-pu rows in order).
// d_out[0..2S) = y, d_out[2S..4S) = y2.

#define THREADS 256
#define TILE    256
#define NTILES  4
#define CHUNK   (TILE * NTILES)      // 1024 tokens per block
#define MAXB    65537

__device__ int g_lb0[MAXB];

// ---- streaming scatter: g_lb0[j] = lower_bound(pu, j*CHUNK) ----
__global__ void lb_scatter(const int* __restrict__ pu, int P, int nblocks)
{
    const int i = blockIdx.x * blockDim.x + threadIdx.x;
    if (i >= P) return;
    const int cur = __ldg(pu + i);
    const int nxt = (i + 1 < P) ? __ldg(pu + i + 1) : 0x7fffffff;
    if (i == 0) {
        for (int j = 0; j <= nblocks && j * CHUNK <= cur; j++) g_lb0[j] = 0;
    }
    for (int j = cur / CHUNK + 1; j <= nblocks && j * CHUNK <= nxt; j++) g_lb0[j] = i + 1;
}

__device__ __forceinline__ void cp_async16(uint32_t smem_dst, const void* gptr) {
    asm volatile("cp.async.cg.shared.global [%0], [%1], 16;\n" :: "r"(smem_dst), "l"(gptr));
}
__device__ __forceinline__ void cp_commit() { asm volatile("cp.async.commit_group;\n"); }
template<int N> __device__ __forceinline__ void cp_wait() {
    asm volatile("cp.async.wait_group %0;\n" :: "n"(N));
}

__global__ __launch_bounds__(THREADS)
void verblizer_kernel(const float*  __restrict__ x,
                      const float*  __restrict__ h,
                      const float*  __restrict__ W,
                      const float*  __restrict__ b,
                      const int*    __restrict__ pu,
                      int S, int P,
                      float* __restrict__ out)
{
    __shared__ float4 sx[2][TILE * 5];   // 2 x 20KB staged x tiles
    __shared__ int    spu[CHUNK];        // 4KB pu window
    __shared__ float4 sW[20];
    __shared__ float2 sB[20];

    const int tid = threadIdx.x;
    const int bs  = blockIdx.x * CHUNK;
    const int lb0 = g_lb0[blockIdx.x];
    const int n   = g_lb0[blockIdx.x + 1] - lb0;   // pu entries in this block's window

    if (tid < 20) {
        sW[tid] = reinterpret_cast<const float4*>(W)[tid];
        sB[tid] = reinterpret_cast<const float2*>(b)[tid];
    }
    for (int i = tid; i < n; i += THREADS) spu[i] = __ldg(pu + lb0 + i);

    const char* __restrict__ xb = reinterpret_cast<const char*>(x);
    const float2* __restrict__ h2 = reinterpret_cast<const float2*>(h);
    float2* __restrict__ outy  = reinterpret_cast<float2*>(out);
    float2* __restrict__ outy2 = reinterpret_cast<float2*>(out + (size_t)2 * S);

    // ---- stage tile 0 ----
    {
        const int tb  = bs;
        const int vt  = min(TILE, S - tb);
        const int vt5 = vt * 5;
        uint32_t dst = (uint32_t)__cvta_generic_to_shared(&sx[0][0]);
        #pragma unroll
        for (int r = 0; r < 5; r++) {
            const int c = tid + r * THREADS;
            if (c < vt5) cp_async16(dst + c * 16, xb + (size_t)tb * 80 + (size_t)c * 16);
        }
        cp_commit();
    }

    #pragma unroll
    for (int t = 0; t < NTILES; t++) {
        // prefetch next tile into the other buffer
        if (t + 1 < NTILES) {
            const int tb  = bs + (t + 1) * TILE;
            const int vt  = min(TILE, S - tb);
            const int vt5 = vt * 5;
            uint32_t dst = (uint32_t)__cvta_generic_to_shared(&sx[(t + 1) & 1][0]);
            #pragma unroll
            for (int r = 0; r < 5; r++) {
                const int c = tid + r * THREADS;
                if (c < vt5) cp_async16(dst + c * 16, xb + (size_t)tb * 80 + (size_t)c * 16);
            }
            cp_commit();
            cp_wait<1>();
        } else {
            cp_wait<0>();
        }
        __syncthreads();

        const int s = bs + t * TILE + tid;
        if (s < S) {
            const float4* __restrict__ row = &sx[t & 1][tid * 5];

            // ---- exact argmax over 20 f32 (first-index tie-break) ----
            const float4 q0 = row[0], q1 = row[1], q2 = row[2], q3 = row[3], q4 = row[4];
            const float g0 = fmaxf(fmaxf(q0.x, q0.y), fmaxf(q0.z, q0.w));
            const float g1 = fmaxf(fmaxf(q1.x, q1.y), fmaxf(q1.z, q1.w));
            const float g2 = fmaxf(fmaxf(q2.x, q2.y), fmaxf(q2.z, q2.w));
            const float g3 = fmaxf(fmaxf(q3.x, q3.y), fmaxf(q3.z, q3.w));
            const float g4 = fmaxf(fmaxf(q4.x, q4.y), fmaxf(q4.z, q4.w));
            const float M  = fmaxf(g4, fmaxf(fmaxf(g0, g1), fmaxf(g2, g3)));

            int gi = 4;
            gi = (g3 == M) ? 3 : gi;
            gi = (g2 == M) ? 2 : gi;
            gi = (g1 == M) ? 1 : gi;
            gi = (g0 == M) ? 0 : gi;

            const float4 qw = row[gi];           // LDS reload of winning quad
            int li = 3;
            li = (qw.z == M) ? 2 : li;
            li = (qw.y == M) ? 1 : li;
            li = (qw.x == M) ? 0 : li;
            const int e = gi * 4 + li;

            // ---- expert Linear(2,2) + softmax(2) ----
            const float2 hv = h2[s];
            const float4 w  = sW[e];
            const float2 bb = sB[e];
            const float y0 = fmaf(hv.x, w.x, fmaf(hv.y, w.y, bb.x));
            const float y1 = fmaf(hv.x, w.z, fmaf(hv.y, w.w, bb.y));
            const float ed  = __expf(y1 - y0);
            const float inv = __fdividef(1.0f, 1.0f + ed);
            float2 yo;
            yo.x = inv;
            yo.y = ed * inv;

            outy[s] = yo;

            // ---- permutation destination: lb = lb0 + lower_bound(spu, s) ----
            int lo = 0, hi = n;
            while (lo < hi) {
                int mid = (lo + hi) >> 1;
                if (spu[mid] < s) lo = mid + 1; else hi = mid;
            }
            const int  cur  = (lo < n) ? spu[lo] : 0x7fffffff;
            const bool ispu = (cur == s);
            const int  dest = ispu ? (lb0 + lo) : (P + s - lb0 - lo);
            outy2[dest] = yo;
        }
        __syncthreads();
    }
}

extern "C" void kernel_launch(void* const* d_in, const int* in_sizes, int n_in,
                              void* d_out, int out_size)
{
    const float* x  = (const float*)d_in[0];   // [1, S, 20]
    const float* h  = (const float*)d_in[1];   // [S, 2]
    const float* W  = (const float*)d_in[2];   // [20, 2, 2]
    const float* b  = (const float*)d_in[3];   // [20, 2]
    const int*   pu = (const int*)  d_in[4];   // [P]

    const int S = in_sizes[1] / 2;
    const int P = in_sizes[4];
    const int blocks = (S + CHUNK - 1) / CHUNK;

    lb_scatter<<<(P + 255) / 256, 256>>>(pu, P, blocks);
    verblizer_kernel<<<blocks, THREADS>>>(x, h, W, b, pu, S, P, (float*)d_out);
}